// round 14
// baseline (speedup 1.0000x reference)
#include <cuda_runtime.h>
#include <cstdint>
#include <cstddef>

// Problem dims
#define Bn 64
#define Tn 2048
#define Fn 256
#define Hn 512
#define On 128

// Fused recurrence partition: 8 groups x 8 batches, 16 slices x 32 cols = 128 CTAs
#define NG 8
#define GB 8
#define NS 16
#define NKG 16
#define KC 32
#define SC 32
#define NTHR 512
#define WSTRIDE 516       // padded W_ih1 row stride (16B-aligned)
#define NWORK 20          // persistent GEMM worker blocks (SMs 128..147)
#define NTILES 4096       // (Bn*Tn/128) row-blocks x (Hn/128) col-blocks
#define NTC 16            // t-chunks of 128 steps
#define BOOT 256          // chunk-0 tiles bootstrapped by recurrence CTAs (2 each)

// ---------------- static device workspaces -------------------------------------
__device__ __align__(128) float g_xp[(size_t)Bn * Tn * Hn];      // 256 MB input proj
__device__ __align__(128) float g_h0buf[2][NG][GB * Hn];         // parity-buffered h0
__device__ __align__(128) float g_h1buf[2][NG][GB * Hn];         // parity-buffered h1
__device__ __align__(128) float g_hT[Bn * Hn];
__device__ unsigned g_flags0[NG][NS];
__device__ unsigned g_flags1[NG][NS];
__device__ unsigned g_tc_done[NTC];   // xp tiles completed per t-chunk (monotonic)

typedef unsigned long long u64t;

// ---------------- packed fp32x2 + sync helpers ----------------------------------
__device__ __forceinline__ u64t fma2(u64t a, u64t b, u64t c) {
    u64t d;
    asm("fma.rn.f32x2 %0, %1, %2, %3;" : "=l"(d) : "l"(a), "l"(b), "l"(c));
    return d;
}
__device__ __forceinline__ u64t pk2(float lo, float hi) {
    u64t r;
    asm("mov.b64 %0, {%1, %2};" : "=l"(r) : "f"(lo), "f"(hi));
    return r;
}
__device__ __forceinline__ float2 upk(u64t v) {
    float2 f;
    asm("mov.b64 {%0, %1}, %2;" : "=f"(f.x), "=f"(f.y) : "l"(v));
    return f;
}
__device__ __forceinline__ unsigned ld_acq(const unsigned* p) {
    unsigned v;
    asm volatile("ld.global.acquire.gpu.u32 %0, [%1];" : "=r"(v) : "l"(p));
    return v;
}
__device__ __forceinline__ void st_rel(unsigned* p, unsigned v) {
    asm volatile("st.global.release.gpu.u32 [%0], %1;" :: "l"(p), "r"(v) : "memory");
}
__device__ __forceinline__ unsigned smem_u32(const void* p) {
    unsigned a;
    asm("{ .reg .u64 t; cvta.to.shared.u64 t, %1; cvt.u32.u64 %0, t; }" : "=r"(a) : "l"(p));
    return a;
}
__device__ __forceinline__ void mbar_init(unsigned m, unsigned cnt) {
    asm volatile("mbarrier.init.shared.b64 [%0], %1;" :: "r"(m), "r"(cnt) : "memory");
}
__device__ __forceinline__ void mbar_expect_tx(unsigned m, unsigned bytes) {
    asm volatile("mbarrier.arrive.expect_tx.shared.b64 _, [%0], %1;" :: "r"(m), "r"(bytes) : "memory");
}
__device__ __forceinline__ void bulk_g2s(unsigned dst, const void* src, unsigned bytes, unsigned m) {
    asm volatile("cp.async.bulk.shared::cluster.global.mbarrier::complete_tx::bytes [%0], [%1], %2, [%3];"
                 :: "r"(dst), "l"(src), "r"(bytes), "r"(m) : "memory");
}
__device__ __forceinline__ void mbar_wait(unsigned m, int phase) {
    asm volatile(
        "{\n\t.reg .pred P;\n"
        "WL%=:\n\t"
        "mbarrier.try_wait.parity.acquire.cta.shared::cta.b64 P, [%0], %1, 0x989680;\n\t"
        "@P bra WD%=;\n\t"
        "bra WL%=;\n"
        "WD%=:\n\t}"
        :: "r"(m), "r"((unsigned)phase) : "memory");
}

// ---------------- one xp GEMM tile: 128 rows x 128 cols x K=256 -----------------
// 512 threads. After the tile is stored, fence + bump g_tc_done[tc].
// Per-output fma order identical to the original sgemm_xp.
__device__ __forceinline__ void gemm_tile(
    const float* __restrict__ A, const float* __restrict__ Wm,
    const float* __restrict__ b1, const float* __restrict__ b2,
    float* smbase, int tau, int tid)
{
    float (*As)[128] = (float (*)[128])smbase;
    float (*Ws)[128] = (float (*)[128])(smbase + 8 * 128);

    const int K = Fn;
    const bool loadA = (tid < 256);
    const int lrow = (tid & 255) >> 1;
    const int lkq = (tid & 1) * 4;
    const int tx = tid & 31, ty = tid >> 5;
    const int m0 = ty * 8, n0 = tx * 4;

    const int tc = tau >> 8;              // t-chunk (0..15)
    const int idx = tau & 255;
    const int bb = idx >> 2;              // batch (0..63)
    const int cn = idx & 3;               // col block (0..3)
    const int bm = bb * 16 + tc;          // row block

    const float* Lg = (loadA ? A + (size_t)(bm * 128 + lrow) * K
                             : Wm + (size_t)(cn * 128 + lrow) * K) + lkq;
    float4 v = *(const float4*)Lg;

    u64t acc[8][2];
#pragma unroll
    for (int i = 0; i < 8; i++) { acc[i][0] = 0ull; acc[i][1] = 0ull; }

    const int nk = K >> 3;                // 32
    float (*S)[128] = loadA ? As : Ws;
    for (int kt = 0; kt < nk; kt++) {
        S[lkq + 0][lrow] = v.x; S[lkq + 1][lrow] = v.y;
        S[lkq + 2][lrow] = v.z; S[lkq + 3][lrow] = v.w;
        __syncthreads();
        if (kt + 1 < nk) v = *(const float4*)(Lg + (size_t)(kt + 1) * 8);
#pragma unroll
        for (int k = 0; k < 8; k++) {
            float4 a0 = *(const float4*)&As[k][m0];
            float4 a1 = *(const float4*)&As[k][m0 + 4];
            ulonglong2 bv = *(const ulonglong2*)&Ws[k][n0];
            float av[8] = {a0.x, a0.y, a0.z, a0.w, a1.x, a1.y, a1.z, a1.w};
#pragma unroll
            for (int i = 0; i < 8; i++) {
                u64t ai = pk2(av[i], av[i]);
                acc[i][0] = fma2(ai, bv.x, acc[i][0]);
                acc[i][1] = fma2(ai, bv.y, acc[i][1]);
            }
        }
        __syncthreads();
    }

    const int gn = cn * 128 + n0;
    float bs[4];
#pragma unroll
    for (int q = 0; q < 4; q++) bs[q] = b1[gn + q] + b2[gn + q];
#pragma unroll
    for (int i = 0; i < 8; i++) {
        float* cp = g_xp + (size_t)(bm * 128 + m0 + i) * Hn + gn;
        float2 p0 = upk(acc[i][0]), p1 = upk(acc[i][1]);
        *(float4*)cp = make_float4(p0.x + bs[0], p0.y + bs[1],
                                   p1.x + bs[2], p1.y + bs[3]);
    }

    __threadfence();                      // gpu-scope: tile writes visible
    __syncthreads();
    if (tid == 0) atomicAdd(&g_tc_done[tc], 1u);
}

// ---------------- single fused launch -------------------------------------------
// Blocks 0..127: bootstrap 2 chunk-0 xp tiles each (256 = all of chunk 0), then
// run R3's fused recurrence with epoch-relative flags and per-chunk xp gates.
// Blocks 128..147: persistent GEMM workers covering tiles 256..4095.
// 148 blocks = one per SM. All producers proceed unconditionally -> no deadlock.
__global__ __launch_bounds__(NTHR, 1) void fused_all(
    const float* __restrict__ x,
    const float* __restrict__ Wih0,
    const float* __restrict__ bih0, const float* __restrict__ bhh0,
    const float* __restrict__ Whh0, const float* __restrict__ Wih1,
    const float* __restrict__ Whh1,
    const float* __restrict__ bih1, const float* __restrict__ bhh1,
    const float* __restrict__ h00, const float* __restrict__ h01)
{
    extern __shared__ float sm[];
    const int tid = threadIdx.x;

    if (blockIdx.x >= NG * NS) {
        // persistent workers: tiles 256..4095 in t-chunk-major order
        const int w = blockIdx.x - NG * NS;
        for (int tau = BOOT + w; tau < NTILES; tau += NWORK)
            gemm_tile(x, Wih0, bih0, bhh0, sm, tau, tid);
        return;
    }

    float* wih1  = sm;                 // SC*WSTRIDE = 16512 floats
    float* shh0  = sm + SC * WSTRIDE;  // 2 x 4096 (parity)
    float* shh1  = shh0 + 2 * GB * Hn; // 2 x 4096 (parity)
    float* part0 = shh1 + 2 * GB * Hn; // NKG*256 = 4096
    float* part1 = part0 + NKG * 256;  // 4096
    __shared__ __align__(8) unsigned long long mbar[2];
    __shared__ unsigned sb0, sb1;
    __shared__ unsigned stcb[NTC];

    const int slice = blockIdx.x & (NS - 1);
    const int group = blockIdx.x >> 4;

    // epoch bases FIRST: all reads land within ~2us of wave-1 dispatch; the
    // earliest counter increment (one full GEMM tile + fence) is >=5us later.
    if (tid == 0) {
        sb0 = *(volatile unsigned*)&g_flags0[group][slice];
        sb1 = *(volatile unsigned*)&g_flags1[group][slice];
    }
    if (tid < NTC) stcb[tid] = *(volatile unsigned*)&g_tc_done[tid];
    __syncthreads();

    // ---- bootstrap: this CTA computes 2 chunk-0 xp tiles (SMEM used as scratch)
    gemm_tile(x, Wih0, bih0, bhh0, sm, 2 * blockIdx.x, tid);
    gemm_tile(x, Wih0, bih0, bhh0, sm, 2 * blockIdx.x + 1, tid);
    __syncthreads();   // scratch dead; init may now overwrite SMEM

    const int j = tid & 31;
    const int kg = tid >> 5;
    const int col = slice * SC + j;
    const int kb = kg * KC;

    // recurrence weights into registers (32 floats per matrix per thread)
    u64t w0[16], w1[16];
    {
        const ulonglong2* p0 = (const ulonglong2*)(Whh0 + (size_t)col * Hn + kb);
        const ulonglong2* p1 = (const ulonglong2*)(Whh1 + (size_t)col * Hn + kb);
#pragma unroll
        for (int i = 0; i < 8; i++) {
            ulonglong2 a = p0[i]; w0[2 * i] = a.x; w0[2 * i + 1] = a.y;
            ulonglong2 b = p1[i]; w1[2 * i] = b.x; w1[2 * i + 1] = b.y;
        }
    }
    // W_ih1 slice into padded SMEM
    for (int idx = tid; idx < SC * Hn; idx += NTHR) {
        int r = idx >> 9, k = idx & 511;
        wih1[r * WSTRIDE + k] = Wih1[(size_t)(slice * SC + r) * Hn + k];
    }
    // preload: parity0 of shh0 = h00 (iter 0 input); parity1 of shh1 = h01
    for (int idx = tid; idx < GB * Hn; idx += NTHR) {
        shh0[idx] = h00[idx & 511];
        shh1[GB * Hn + idx] = h01[idx & 511];
    }

    const unsigned mb0 = smem_u32(&mbar[0]);
    const unsigned mb1 = smem_u32(&mbar[1]);
    const unsigned sh0a = smem_u32(shh0);
    const unsigned sh1a = smem_u32(shh1);
    const unsigned HBYTES = GB * Hn * 4;  // 16384
    if (tid == 0) {
        mbar_init(mb0, 1);
        mbar_init(mb1, 1);
        asm volatile("fence.proxy.async.shared::cta;" ::: "memory");
    }

    // reduce/publish role: thread tid<256 -> (batch rb, col rj)
    const int rb = tid >> 5, rj = tid & 31;          // valid for tid<256
    const int rcol = slice * SC + rj;
    const float bias1 = bih1[rcol] + bhh1[rcol];
    const size_t xbase = ((size_t)(group * GB + rb) * Tn) * Hn + rcol;
    unsigned* f0 = &g_flags0[group][0];
    unsigned* f1 = &g_flags1[group][0];
    __syncthreads();

    const unsigned base0 = sb0, base1 = sb1;

    // gate: all 256 chunk-0 tiles (bootstrapped by the 128 recurrence CTAs)
    if (tid == 0) {
        const unsigned tgt = stcb[0] + 256u;
        while (ld_acq(&g_tc_done[0]) < tgt) {}
    }
    __syncthreads();
    float xpv = (tid < 256) ? __ldg(g_xp + xbase) : 0.f;

    int ph0 = 0, ph1 = 0;
    u64t acc[8];

#pragma unroll 1
    for (int t = 0; t <= Tn; t++) {
        const int cur = t & 1, nxt = cur ^ 1;
        const float* h0c = shh0 + cur * (GB * Hn);
        const float* h1c = shh1 + cur * (GB * Hn);

        // shh0[cur] = h0_{t-1}: wait for the bulk copy issued last iteration
        if (t > 0) { mbar_wait(mb0, ph0); ph0 ^= 1; }

        if (t < Tn) {
            // ---- mv0 = W_hh0 . h0_{t-1}
#pragma unroll
            for (int b = 0; b < 8; b++) acc[b] = 0ull;
#pragma unroll
            for (int ii = 0; ii < 8; ii++) {
#pragma unroll
                for (int b = 0; b < 8; b++) {
                    ulonglong2 h2 = *(const ulonglong2*)(h0c + b * Hn + kb + ii * 4);
                    acc[b] = fma2(w0[2 * ii],     h2.x, acc[b]);
                    acc[b] = fma2(w0[2 * ii + 1], h2.y, acc[b]);
                }
            }
#pragma unroll
            for (int b = 0; b < 8; b++) {
                float2 f = upk(acc[b]);
                part0[kg * 256 + b * 32 + j] = f.x + f.y;
            }
            __syncthreads();
            if (tid < 256) {
                float s0 = xpv, s1 = 0.f;
#pragma unroll
                for (int kk = 0; kk < 16; kk += 2) {
                    s0 += part0[kk * 256 + tid];
                    s1 += part0[(kk + 1) * 256 + tid];
                }
                float hn = tanhf(s0 + s1);
                __stcg(&g_h0buf[cur][group][rb * Hn + rcol], hn);
                if (t + 1 < Tn) {
                    // gate the next t-chunk of xp (once per 128 steps)
                    if (((t + 1) & 127) == 0) {
                        const int tcn = (t + 1) >> 7;
                        const unsigned tgt = stcb[tcn] + 256u;
                        while (ld_acq(&g_tc_done[tcn]) < tgt) {}
                    }
                    xpv = __ldg(g_xp + xbase + (size_t)(t + 1) * Hn);
                }
            }
            __syncthreads();
            if (tid == 0) st_rel(&f0[slice], base0 + (unsigned)(t + 1));
        }

        if (t > 0) {
            // shh1[cur] = h1_{t-2} (preloaded for t==1, bulk-copied for t>=2)
            if (t >= 2) { mbar_wait(mb1, ph1); ph1 ^= 1; }

            // ---- mvB = W_hh1 . h1_{t-2}
#pragma unroll
            for (int b = 0; b < 8; b++) acc[b] = 0ull;
#pragma unroll
            for (int ii = 0; ii < 8; ii++) {
#pragma unroll
                for (int b = 0; b < 8; b++) {
                    ulonglong2 h2 = *(const ulonglong2*)(h1c + b * Hn + kb + ii * 4);
                    acc[b] = fma2(w1[2 * ii],     h2.x, acc[b]);
                    acc[b] = fma2(w1[2 * ii + 1], h2.y, acc[b]);
                }
            }

            // ---- kick h0_t -> shh0[nxt] bulk copy (hidden under mvC)
            if (t < Tn && tid < 32) {
                if (tid < 16) { while (ld_acq(&f0[tid]) < base0 + (unsigned)(t + 1)) {} }
                __syncwarp();
                if (tid == 0) {
                    mbar_expect_tx(mb0, HBYTES);
                    bulk_g2s(sh0a + nxt * HBYTES, &g_h0buf[cur][group][0], HBYTES, mb0);
                }
            }

            // ---- mvC = W_ih1 . h0_{t-1}, accumulated on top of mvB
            {
                const float* wr = wih1 + j * WSTRIDE + kb;
#pragma unroll
                for (int ii = 0; ii < 8; ii++) {
                    ulonglong2 w2 = *(const ulonglong2*)(wr + ii * 4);
#pragma unroll
                    for (int b = 0; b < 8; b++) {
                        ulonglong2 h2 = *(const ulonglong2*)(h0c + b * Hn + kb + ii * 4);
                        acc[b] = fma2(w2.x, h2.x, acc[b]);
                        acc[b] = fma2(w2.y, h2.y, acc[b]);
                    }
                }
            }
#pragma unroll
            for (int b = 0; b < 8; b++) {
                float2 f = upk(acc[b]);
                part1[kg * 256 + b * 32 + j] = f.x + f.y;
            }
            __syncthreads();
            if (tid < 256) {
                float s0 = bias1, s1 = 0.f;
#pragma unroll
                for (int kk = 0; kk < 16; kk += 2) {
                    s0 += part1[kk * 256 + tid];
                    s1 += part1[(kk + 1) * 256 + tid];
                }
                float hn = tanhf(s0 + s1);
                if (t < Tn) __stcg(&g_h1buf[cur][group][rb * Hn + rcol], hn);
                else        g_hT[(group * GB + rb) * Hn + rcol] = hn;
            }
            __syncthreads();
            if (t < Tn) {
                if (tid == 0) st_rel(&f1[slice], base1 + (unsigned)t);
                // kick h1_{t-1} -> shh1[nxt] copy; consumed after next iter's mv0
                if (tid < 32) {
                    if (tid < 16) { while (ld_acq(&f1[tid]) < base1 + (unsigned)t) {} }
                    __syncwarp();
                    if (tid == 0) {
                        mbar_expect_tx(mb1, HBYTES);
                        bulk_g2s(sh1a + nxt * HBYTES, &g_h1buf[cur][group][0], HBYTES, mb1);
                    }
                }
            }
        } else {
            // t == 0: kick the very first h0 copy
            if (tid < 32) {
                if (tid < 16) { while (ld_acq(&f0[tid]) < base0 + 1u) {} }
                __syncwarp();
                if (tid == 0) {
                    mbar_expect_tx(mb0, HBYTES);
                    bulk_g2s(sh0a + HBYTES, &g_h0buf[0][group][0], HBYTES, mb0);
                }
            }
        }
    }
}

// ---------------- final FC ------------------------------------------------------
__global__ __launch_bounds__(128) void fc_kernel(
    const float* __restrict__ Wfc, const float* __restrict__ bfc,
    float* __restrict__ out)
{
    __shared__ float hs[Hn];
    const int b = blockIdx.x, tid = threadIdx.x;
    ((float4*)hs)[tid] = *(const float4*)&g_hT[b * Hn + tid * 4];
    __syncthreads();
    const float4* wr = (const float4*)(Wfc + (size_t)tid * Hn);
    float acc = 0.f;
#pragma unroll 8
    for (int i = 0; i < Hn / 4; i++) {
        float4 w = __ldg(&wr[i]);
        float4 h = ((const float4*)hs)[i];
        acc += w.x * h.x + w.y * h.y + w.z * h.z + w.w * h.w;
    }
    out[b * On + tid] = acc + bfc[tid];
}

// ---------------- launcher ------------------------------------------------------
extern "C" void kernel_launch(void* const* d_in, const int* in_sizes, int n_in,
                              void* d_out, int out_size)
{
    (void)in_sizes; (void)n_in; (void)out_size;
    const float* x     = (const float*)d_in[0];
    const float* W_ih0 = (const float*)d_in[1];
    const float* W_hh0 = (const float*)d_in[2];
    const float* b_ih0 = (const float*)d_in[3];
    const float* b_hh0 = (const float*)d_in[4];
    const float* h0_0  = (const float*)d_in[5];
    const float* W_ih1 = (const float*)d_in[6];
    const float* W_hh1 = (const float*)d_in[7];
    const float* b_ih1 = (const float*)d_in[8];
    const float* b_hh1 = (const float*)d_in[9];
    const float* h0_1  = (const float*)d_in[10];
    const float* W_fc  = (const float*)d_in[11];
    const float* b_fc  = (const float*)d_in[12];
    float* out = (float*)d_out;

    const int fused_smem =
        (SC * WSTRIDE + 4 * GB * Hn + 2 * NKG * 256) * sizeof(float);
    cudaFuncSetAttribute(fused_all, cudaFuncAttributeMaxDynamicSharedMemorySize, fused_smem);

    // one launch: 128 recurrence CTAs (bootstrap chunk-0 xp, then recurrence)
    // + 20 persistent xp-GEMM workers (tiles 256..4095). 148 blocks = 148 SMs.
    fused_all<<<NG * NS + NWORK, NTHR, fused_smem>>>(
        x, W_ih0, b_ih0, b_hh0,
        W_hh0, W_ih1, W_hh1, b_ih1, b_hh1, h0_0, h0_1);

    // head
    fc_kernel<<<Bn, 128>>>(W_fc, b_fc, out);
}

// round 15
// speedup vs baseline: 1.0562x; 1.0562x over previous
#include <cuda_runtime.h>
#include <cstdint>
#include <cstddef>

// Problem dims
#define Bn 64
#define Tn 2048
#define Fn 256
#define Hn 512
#define On 128

// Fused recurrence partition: 8 groups x 8 batches, 16 slices x 32 cols = 128 CTAs
#define NG 8
#define GB 8
#define NS 16
#define NKG 16
#define KC 32
#define SC 32
#define NTHR 512
#define WSTRIDE 516       // padded W_ih1 row stride (16B-aligned)
#define NWORK 20          // persistent GEMM worker blocks (SMs 128..147)
#define NTILES 4096       // (Bn*Tn/128) row-blocks x (Hn/128) col-blocks
#define NTC 16            // t-chunks of 128 steps

// ---------------- static device workspaces -------------------------------------
__device__ __align__(128) float g_xp[(size_t)Bn * Tn * Hn];      // 256 MB input proj
__device__ __align__(128) float g_h0buf[2][NG][GB * Hn];         // parity-buffered h0
__device__ __align__(128) float g_h1buf[2][NG][GB * Hn];         // parity-buffered h1
__device__ __align__(128) float g_hT[Bn * Hn];
__device__ unsigned g_flags0[NG][NS];
__device__ unsigned g_flags1[NG][NS];
__device__ unsigned g_tc_done[NTC];   // xp tiles completed per t-chunk (monotonic)

typedef unsigned long long u64t;

// ---------------- packed fp32x2 + sync helpers ----------------------------------
__device__ __forceinline__ u64t fma2(u64t a, u64t b, u64t c) {
    u64t d;
    asm("fma.rn.f32x2 %0, %1, %2, %3;" : "=l"(d) : "l"(a), "l"(b), "l"(c));
    return d;
}
__device__ __forceinline__ u64t pk2(float lo, float hi) {
    u64t r;
    asm("mov.b64 %0, {%1, %2};" : "=l"(r) : "f"(lo), "f"(hi));
    return r;
}
__device__ __forceinline__ float2 upk(u64t v) {
    float2 f;
    asm("mov.b64 {%0, %1}, %2;" : "=f"(f.x), "=f"(f.y) : "l"(v));
    return f;
}
__device__ __forceinline__ unsigned ld_acq(const unsigned* p) {
    unsigned v;
    asm volatile("ld.global.acquire.gpu.u32 %0, [%1];" : "=r"(v) : "l"(p));
    return v;
}
__device__ __forceinline__ void st_rel(unsigned* p, unsigned v) {
    asm volatile("st.global.release.gpu.u32 [%0], %1;" :: "l"(p), "r"(v) : "memory");
}
__device__ __forceinline__ unsigned smem_u32(const void* p) {
    unsigned a;
    asm("{ .reg .u64 t; cvta.to.shared.u64 t, %1; cvt.u32.u64 %0, t; }" : "=r"(a) : "l"(p));
    return a;
}
__device__ __forceinline__ void mbar_init(unsigned m, unsigned cnt) {
    asm volatile("mbarrier.init.shared.b64 [%0], %1;" :: "r"(m), "r"(cnt) : "memory");
}
__device__ __forceinline__ void mbar_expect_tx(unsigned m, unsigned bytes) {
    asm volatile("mbarrier.arrive.expect_tx.shared.b64 _, [%0], %1;" :: "r"(m), "r"(bytes) : "memory");
}
__device__ __forceinline__ void bulk_g2s(unsigned dst, const void* src, unsigned bytes, unsigned m) {
    asm volatile("cp.async.bulk.shared::cluster.global.mbarrier::complete_tx::bytes [%0], [%1], %2, [%3];"
                 :: "r"(dst), "l"(src), "r"(bytes), "r"(m) : "memory");
}
__device__ __forceinline__ void mbar_wait(unsigned m, int phase) {
    asm volatile(
        "{\n\t.reg .pred P;\n"
        "WL%=:\n\t"
        "mbarrier.try_wait.parity.acquire.cta.shared::cta.b64 P, [%0], %1, 0x989680;\n\t"
        "@P bra WD%=;\n\t"
        "bra WL%=;\n"
        "WD%=:\n\t}"
        :: "r"(m), "r"((unsigned)phase) : "memory");
}

// ---------------- GEMM worker: persistent, t-chunk-ordered xp producer ----------
// 512 threads per block. Tile = 128 rows x 128 cols x K=256. Each worker walks
// tiles in increasing index -> t-chunk-major order; after each tile it fences and
// bumps g_tc_done[tc]. xp stores use evict-first (.cs) — written once, consumed
// milliseconds later — so worker traffic doesn't evict the recurrence's L2 set.
__device__ void gemm_worker(
    const float* __restrict__ A, const float* __restrict__ Wm,
    const float* __restrict__ b1, const float* __restrict__ b2,
    float* smbase)
{
    float (*As)[128] = (float (*)[128])smbase;
    float (*Ws)[128] = (float (*)[128])(smbase + 8 * 128);

    const int tid = threadIdx.x;
    const int w = blockIdx.x - NG * NS;      // 0..NWORK-1
    const int K = Fn;
    const bool loadA = (tid < 256);
    const int lrow = (tid & 255) >> 1;
    const int lkq = (tid & 1) * 4;
    const int tx = tid & 31, ty = tid >> 5;
    const int m0 = ty * 8, n0 = tx * 4;

    for (int tau = w; tau < NTILES; tau += NWORK) {
        const int tc = tau >> 8;              // t-chunk (0..15)
        const int idx = tau & 255;
        const int bb = idx >> 2;              // batch (0..63)
        const int cn = idx & 3;               // col block (0..3)
        const int bm = bb * 16 + tc;          // row block: rows = bb*2048 + tc*128 ..

        const float* Lg = (loadA ? A + (size_t)(bm * 128 + lrow) * K
                                 : Wm + (size_t)(cn * 128 + lrow) * K) + lkq;
        float4 v = *(const float4*)Lg;

        u64t acc[8][2];
#pragma unroll
        for (int i = 0; i < 8; i++) { acc[i][0] = 0ull; acc[i][1] = 0ull; }

        const int nk = K >> 3;                // 32
        float (*S)[128] = loadA ? As : Ws;
        for (int kt = 0; kt < nk; kt++) {
            S[lkq + 0][lrow] = v.x; S[lkq + 1][lrow] = v.y;
            S[lkq + 2][lrow] = v.z; S[lkq + 3][lrow] = v.w;
            __syncthreads();
            if (kt + 1 < nk) v = *(const float4*)(Lg + (size_t)(kt + 1) * 8);
#pragma unroll
            for (int k = 0; k < 8; k++) {
                float4 a0 = *(const float4*)&As[k][m0];
                float4 a1 = *(const float4*)&As[k][m0 + 4];
                ulonglong2 bv = *(const ulonglong2*)&Ws[k][n0];
                float av[8] = {a0.x, a0.y, a0.z, a0.w, a1.x, a1.y, a1.z, a1.w};
#pragma unroll
                for (int i = 0; i < 8; i++) {
                    u64t ai = pk2(av[i], av[i]);
                    acc[i][0] = fma2(ai, bv.x, acc[i][0]);
                    acc[i][1] = fma2(ai, bv.y, acc[i][1]);
                }
            }
            __syncthreads();
        }

        const int gn = cn * 128 + n0;
        float bs[4];
#pragma unroll
        for (int q = 0; q < 4; q++) bs[q] = b1[gn + q] + b2[gn + q];
#pragma unroll
        for (int i = 0; i < 8; i++) {
            float* cp = g_xp + (size_t)(bm * 128 + m0 + i) * Hn + gn;
            float2 p0 = upk(acc[i][0]), p1 = upk(acc[i][1]);
            __stcs((float4*)cp, make_float4(p0.x + bs[0], p0.y + bs[1],
                                            p1.x + bs[2], p1.y + bs[3]));
        }

        __threadfence();                      // gpu-scope: tile writes visible
        __syncthreads();
        if (tid == 0) atomicAdd(&g_tc_done[tc], 1u);
    }
}

// ---------------- single fused launch: recurrence CTAs + GEMM workers -----------
// Blocks 0..127: R3's fused recurrence, byte-for-byte, with epoch-relative flags
// and a once-per-128-steps gate on g_tc_done before consuming the next xp chunk.
// Blocks 128..147: persistent GEMM workers. 148 blocks = one per SM (wave-1
// bijective placement); workers never wait on the recurrence -> deadlock-free.
__global__ __launch_bounds__(NTHR, 1) void fused_all(
    const float* __restrict__ x,
    const float* __restrict__ Wih0,
    const float* __restrict__ bih0, const float* __restrict__ bhh0,
    const float* __restrict__ Whh0, const float* __restrict__ Wih1,
    const float* __restrict__ Whh1,
    const float* __restrict__ bih1, const float* __restrict__ bhh1,
    const float* __restrict__ h00, const float* __restrict__ h01)
{
    extern __shared__ float sm[];

    if (blockIdx.x >= NG * NS) {
        gemm_worker(x, Wih0, bih0, bhh0, sm);
        return;
    }

    float* wih1  = sm;                 // SC*WSTRIDE = 16512 floats
    float* shh0  = sm + SC * WSTRIDE;  // 2 x 4096 (parity)
    float* shh1  = shh0 + 2 * GB * Hn; // 2 x 4096 (parity)
    float* part0 = shh1 + 2 * GB * Hn; // NKG*256 = 4096
    float* part1 = part0 + NKG * 256;  // 4096
    __shared__ __align__(8) unsigned long long mbar[2];
    __shared__ unsigned sb0, sb1;
    __shared__ unsigned stcb[NTC];

    const int tid = threadIdx.x;
    const int slice = blockIdx.x & (NS - 1);
    const int group = blockIdx.x >> 4;

    // epoch bases FIRST (flags/counters are uniform at launch; workers' first
    // increment lands >= ~18us later, far after this read)
    if (tid == 0) {
        sb0 = *(volatile unsigned*)&g_flags0[group][slice];
        sb1 = *(volatile unsigned*)&g_flags1[group][slice];
    }
    if (tid < NTC) stcb[tid] = *(volatile unsigned*)&g_tc_done[tid];

    const int j = tid & 31;
    const int kg = tid >> 5;
    const int col = slice * SC + j;
    const int kb = kg * KC;

    // recurrence weights into registers (32 floats per matrix per thread)
    u64t w0[16], w1[16];
    {
        const ulonglong2* p0 = (const ulonglong2*)(Whh0 + (size_t)col * Hn + kb);
        const ulonglong2* p1 = (const ulonglong2*)(Whh1 + (size_t)col * Hn + kb);
#pragma unroll
        for (int i = 0; i < 8; i++) {
            ulonglong2 a = p0[i]; w0[2 * i] = a.x; w0[2 * i + 1] = a.y;
            ulonglong2 b = p1[i]; w1[2 * i] = b.x; w1[2 * i + 1] = b.y;
        }
    }
    // W_ih1 slice into padded SMEM
    for (int idx = tid; idx < SC * Hn; idx += NTHR) {
        int r = idx >> 9, k = idx & 511;
        wih1[r * WSTRIDE + k] = Wih1[(size_t)(slice * SC + r) * Hn + k];
    }
    // preload: parity0 of shh0 = h00 (iter 0 input); parity1 of shh1 = h01
    for (int idx = tid; idx < GB * Hn; idx += NTHR) {
        shh0[idx] = h00[idx & 511];
        shh1[GB * Hn + idx] = h01[idx & 511];
    }

    const unsigned mb0 = smem_u32(&mbar[0]);
    const unsigned mb1 = smem_u32(&mbar[1]);
    const unsigned sh0a = smem_u32(shh0);
    const unsigned sh1a = smem_u32(shh1);
    const unsigned HBYTES = GB * Hn * 4;  // 16384
    if (tid == 0) {
        mbar_init(mb0, 1);
        mbar_init(mb1, 1);
        asm volatile("fence.proxy.async.shared::cta;" ::: "memory");
    }

    // reduce/publish role: thread tid<256 -> (batch rb, col rj)
    const int rb = tid >> 5, rj = tid & 31;          // valid for tid<256
    const int rcol = slice * SC + rj;
    const float bias1 = bih1[rcol] + bhh1[rcol];
    const size_t xbase = ((size_t)(group * GB + rb) * Tn) * Hn + rcol;
    unsigned* f0 = &g_flags0[group][0];
    unsigned* f1 = &g_flags1[group][0];
    __syncthreads();

    const unsigned base0 = sb0, base1 = sb1;

    // gate: t-chunk 0 of xp must be complete before consuming xp[:,0,:]
    if (tid == 0) {
        const unsigned tgt = stcb[0] + 256u;
        while (ld_acq(&g_tc_done[0]) < tgt) {}
    }
    __syncthreads();
    float xpv = (tid < 256) ? __ldcs(g_xp + xbase) : 0.f;

    int ph0 = 0, ph1 = 0;
    u64t acc[8];

#pragma unroll 1
    for (int t = 0; t <= Tn; t++) {
        const int cur = t & 1, nxt = cur ^ 1;
        const float* h0c = shh0 + cur * (GB * Hn);
        const float* h1c = shh1 + cur * (GB * Hn);

        // shh0[cur] = h0_{t-1}: wait for the bulk copy issued last iteration
        if (t > 0) { mbar_wait(mb0, ph0); ph0 ^= 1; }

        if (t < Tn) {
            // ---- mv0 = W_hh0 . h0_{t-1}
#pragma unroll
            for (int b = 0; b < 8; b++) acc[b] = 0ull;
#pragma unroll
            for (int ii = 0; ii < 8; ii++) {
#pragma unroll
                for (int b = 0; b < 8; b++) {
                    ulonglong2 h2 = *(const ulonglong2*)(h0c + b * Hn + kb + ii * 4);
                    acc[b] = fma2(w0[2 * ii],     h2.x, acc[b]);
                    acc[b] = fma2(w0[2 * ii + 1], h2.y, acc[b]);
                }
            }
#pragma unroll
            for (int b = 0; b < 8; b++) {
                float2 f = upk(acc[b]);
                part0[kg * 256 + b * 32 + j] = f.x + f.y;
            }
            __syncthreads();
            if (tid < 256) {
                float s0 = xpv, s1 = 0.f;
#pragma unroll
                for (int kk = 0; kk < 16; kk += 2) {
                    s0 += part0[kk * 256 + tid];
                    s1 += part0[(kk + 1) * 256 + tid];
                }
                float hn = tanhf(s0 + s1);
                __stcg(&g_h0buf[cur][group][rb * Hn + rcol], hn);
                if (t + 1 < Tn) {
                    // gate the next t-chunk of xp (once per 128 steps)
                    if (((t + 1) & 127) == 0) {
                        const int tcn = (t + 1) >> 7;
                        const unsigned tgt = stcb[tcn] + 256u;
                        while (ld_acq(&g_tc_done[tcn]) < tgt) {}
                    }
                    xpv = __ldcs(g_xp + xbase + (size_t)(t + 1) * Hn);
                }
            }
            __syncthreads();
            if (tid == 0) st_rel(&f0[slice], base0 + (unsigned)(t + 1));
        }

        if (t > 0) {
            // shh1[cur] = h1_{t-2} (preloaded for t==1, bulk-copied for t>=2)
            if (t >= 2) { mbar_wait(mb1, ph1); ph1 ^= 1; }

            // ---- mvB = W_hh1 . h1_{t-2}
#pragma unroll
            for (int b = 0; b < 8; b++) acc[b] = 0ull;
#pragma unroll
            for (int ii = 0; ii < 8; ii++) {
#pragma unroll
                for (int b = 0; b < 8; b++) {
                    ulonglong2 h2 = *(const ulonglong2*)(h1c + b * Hn + kb + ii * 4);
                    acc[b] = fma2(w1[2 * ii],     h2.x, acc[b]);
                    acc[b] = fma2(w1[2 * ii + 1], h2.y, acc[b]);
                }
            }

            // ---- kick h0_t -> shh0[nxt] bulk copy (hidden under mvC)
            if (t < Tn && tid < 32) {
                if (tid < 16) { while (ld_acq(&f0[tid]) < base0 + (unsigned)(t + 1)) {} }
                __syncwarp();
                if (tid == 0) {
                    mbar_expect_tx(mb0, HBYTES);
                    bulk_g2s(sh0a + nxt * HBYTES, &g_h0buf[cur][group][0], HBYTES, mb0);
                }
            }

            // ---- mvC = W_ih1 . h0_{t-1}, accumulated on top of mvB
            {
                const float* wr = wih1 + j * WSTRIDE + kb;
#pragma unroll
                for (int ii = 0; ii < 8; ii++) {
                    ulonglong2 w2 = *(const ulonglong2*)(wr + ii * 4);
#pragma unroll
                    for (int b = 0; b < 8; b++) {
                        ulonglong2 h2 = *(const ulonglong2*)(h0c + b * Hn + kb + ii * 4);
                        acc[b] = fma2(w2.x, h2.x, acc[b]);
                        acc[b] = fma2(w2.y, h2.y, acc[b]);
                    }
                }
            }
#pragma unroll
            for (int b = 0; b < 8; b++) {
                float2 f = upk(acc[b]);
                part1[kg * 256 + b * 32 + j] = f.x + f.y;
            }
            __syncthreads();
            if (tid < 256) {
                float s0 = bias1, s1 = 0.f;
#pragma unroll
                for (int kk = 0; kk < 16; kk += 2) {
                    s0 += part1[kk * 256 + tid];
                    s1 += part1[(kk + 1) * 256 + tid];
                }
                float hn = tanhf(s0 + s1);
                if (t < Tn) __stcg(&g_h1buf[cur][group][rb * Hn + rcol], hn);
                else        g_hT[(group * GB + rb) * Hn + rcol] = hn;
            }
            __syncthreads();
            if (t < Tn) {
                if (tid == 0) st_rel(&f1[slice], base1 + (unsigned)t);
                // kick h1_{t-1} -> shh1[nxt] copy; consumed after next iter's mv0
                if (tid < 32) {
                    if (tid < 16) { while (ld_acq(&f1[tid]) < base1 + (unsigned)t) {} }
                    __syncwarp();
                    if (tid == 0) {
                        mbar_expect_tx(mb1, HBYTES);
                        bulk_g2s(sh1a + nxt * HBYTES, &g_h1buf[cur][group][0], HBYTES, mb1);
                    }
                }
            }
        } else {
            // t == 0: kick the very first h0 copy
            if (tid < 32) {
                if (tid < 16) { while (ld_acq(&f0[tid]) < base0 + 1u) {} }
                __syncwarp();
                if (tid == 0) {
                    mbar_expect_tx(mb0, HBYTES);
                    bulk_g2s(sh0a + HBYTES, &g_h0buf[0][group][0], HBYTES, mb0);
                }
            }
        }
    }
}

// ---------------- final FC ------------------------------------------------------
__global__ __launch_bounds__(128) void fc_kernel(
    const float* __restrict__ Wfc, const float* __restrict__ bfc,
    float* __restrict__ out)
{
    __shared__ float hs[Hn];
    const int b = blockIdx.x, tid = threadIdx.x;
    ((float4*)hs)[tid] = *(const float4*)&g_hT[b * Hn + tid * 4];
    __syncthreads();
    const float4* wr = (const float4*)(Wfc + (size_t)tid * Hn);
    float acc = 0.f;
#pragma unroll 8
    for (int i = 0; i < Hn / 4; i++) {
        float4 w = __ldg(&wr[i]);
        float4 h = ((const float4*)hs)[i];
        acc += w.x * h.x + w.y * h.y + w.z * h.z + w.w * h.w;
    }
    out[b * On + tid] = acc + bfc[tid];
}

// ---------------- launcher ------------------------------------------------------
extern "C" void kernel_launch(void* const* d_in, const int* in_sizes, int n_in,
                              void* d_out, int out_size)
{
    (void)in_sizes; (void)n_in; (void)out_size;
    const float* x     = (const float*)d_in[0];
    const float* W_ih0 = (const float*)d_in[1];
    const float* W_hh0 = (const float*)d_in[2];
    const float* b_ih0 = (const float*)d_in[3];
    const float* b_hh0 = (const float*)d_in[4];
    const float* h0_0  = (const float*)d_in[5];
    const float* W_ih1 = (const float*)d_in[6];
    const float* W_hh1 = (const float*)d_in[7];
    const float* b_ih1 = (const float*)d_in[8];
    const float* b_hh1 = (const float*)d_in[9];
    const float* h0_1  = (const float*)d_in[10];
    const float* W_fc  = (const float*)d_in[11];
    const float* b_fc  = (const float*)d_in[12];
    float* out = (float*)d_out;

    const int fused_smem =
        (SC * WSTRIDE + 4 * GB * Hn + 2 * NKG * 256) * sizeof(float);
    cudaFuncSetAttribute(fused_all, cudaFuncAttributeMaxDynamicSharedMemorySize, fused_smem);

    // one launch: 128 recurrence CTAs + 20 persistent xp-GEMM workers (148 SMs)
    fused_all<<<NG * NS + NWORK, NTHR, fused_smem>>>(
        x, W_ih0, b_ih0, b_hh0,
        W_hh0, W_ih1, W_hh1, b_ih1, b_hh1, h0_0, h0_1);

    // head
    fc_kernel<<<Bn, 128>>>(W_fc, b_fc, out);
}